// round 2
// baseline (speedup 1.0000x reference)
#include <cuda_runtime.h>
#include <math.h>
#include <stdint.h>

#define EN   100000
#define NN   50000
#define HIDN 128
#define PBLK 128   // pooled-reduce partial blocks

// ---------------- scratch (static device arrays; no runtime alloc) ----------
__device__ float g_KV[(size_t)NN * 4 * 512];   // per (node,s): [Ks(128) VWs(128) Kd(128) VWd(128)]
__device__ float g_QL[(size_t)EN * HIDN];      // q_l per edge
__device__ float g_Wstack[512 * 128];          // stacked folded weights (N=512, K=128)
__device__ float g_pp[PBLK * 512];             // pooled partials
__device__ float g_Mg[512];                    // v_g @ wo_g^T  [s][h]
__device__ float g_Gmat[512];                  // [j][s]: wq_g^T @ k_g^T
__device__ float g_cg[4];                      // bq_g . k_g[s]
__device__ float g_cvec[128];                  // wo_l@bv_l + bo_l

// ---------------- 1) pooled mean: partial sums (deterministic 2-stage) ------
__global__ void pool_partial(const float* __restrict__ gf) {
    int b = blockIdx.x, t = threadIdx.x;          // 512 threads
    int rowsPer = (NN + PBLK - 1) / PBLK;
    int r0 = b * rowsPer;
    int r1 = min(NN, r0 + rowsPer);
    float acc = 0.f;
    for (int r = r0; r < r1; r++) acc += gf[(size_t)r * 512 + t];
    g_pp[b * 512 + t] = acc;
}

// ---------------- 2) small precompute (1 block, 128 threads) ----------------
__global__ void pre_small(const float* __restrict__ wk_g, const float* __restrict__ wv_g,
                          const float* __restrict__ wq_g, const float* __restrict__ wo_g,
                          const float* __restrict__ bk_g, const float* __restrict__ bv_g,
                          const float* __restrict__ bq_g,
                          const float* __restrict__ wo_l, const float* __restrict__ bv_l,
                          const float* __restrict__ bo_l,
                          float* __restrict__ dout) {
    __shared__ float sp[512], skg[512], svg[512];
    int t = threadIdx.x;
    // reduce partials (fixed order = deterministic), write pooled output
    for (int c = t; c < 512; c += 128) {
        float s = 0.f;
        for (int b = 0; b < PBLK; b++) s += g_pp[b * 512 + c];
        float p = s * (1.0f / NN);
        sp[c] = p;
        dout[(size_t)EN * 384 + c] = p;   // pooled_global output
    }
    __syncthreads();
    // k_g, v_g
    for (int idx = t; idx < 512; idx += 128) {
        int s = idx >> 7, h = idx & 127;
        float a = 0.f, bsum = 0.f;
        const float* pr = &sp[s * 128];
        for (int j = 0; j < 128; j++) {
            float p = pr[j];
            a    += p * wk_g[h * 128 + j];
            bsum += p * wv_g[h * 128 + j];
        }
        skg[idx] = a + bk_g[h];
        svg[idx] = bsum + bv_g[h];
    }
    __syncthreads();
    // M_g[s][h] = sum_j v_g[s,j] * wo_g[h,j]
    for (int idx = t; idx < 512; idx += 128) {
        int s = idx >> 7, h = idx & 127;
        float m = 0.f;
        for (int j = 0; j < 128; j++) m += svg[s * 128 + j] * wo_g[h * 128 + j];
        g_Mg[idx] = m;
    }
    // Gmat[j][s] = sum_h wq_g[h,j] * k_g[s,h]
    for (int idx = t; idx < 512; idx += 128) {
        int j = idx >> 2, s = idx & 3;
        float g = 0.f;
        for (int h2 = 0; h2 < 128; h2++) g += wq_g[h2 * 128 + j] * skg[s * 128 + h2];
        g_Gmat[idx] = g;
    }
    if (t < 4) {
        float c = 0.f;
        for (int h2 = 0; h2 < 128; h2++) c += bq_g[t * 0 + h2] * skg[t * 128 + h2];
        g_cg[t] = c;
    }
    // cvec = wo_l @ bv_l + bo_l
    {
        float c = 0.f;
        for (int m = 0; m < 128; m++) c += wo_l[t * 128 + m] * bv_l[m];
        g_cvec[t] = c + bo_l[t];
    }
}

// ---------------- 3) build stacked weight matrix (512 x 128) ----------------
__global__ void build_wstack(const float* __restrict__ wk_l, const float* __restrict__ wv_l,
                             const float* __restrict__ wo_l) {
    int n = blockIdx.x, k = threadIdx.x;
    float w;
    if (n < 128) {
        w = wk_l[n * 256 + k];
    } else if (n < 256) {
        int h = n - 128; float s = 0.f;
        for (int m = 0; m < 128; m++) s += wo_l[h * 128 + m] * wv_l[m * 256 + k];
        w = s;
    } else if (n < 384) {
        w = wk_l[(n - 256) * 256 + 128 + k];
    } else {
        int h = n - 384; float s = 0.f;
        for (int m = 0; m < 128; m++) s += wo_l[h * 128 + m] * wv_l[m * 256 + 128 + k];
        w = s;
    }
    g_Wstack[n * 128 + k] = w;
}

// ---------------- 4) tiled fp32 GEMM: C[M,N] = A[M,128] @ W[N,128]^T (+bias) -
// BM=128 BN=64 BK=16, 256 threads, 8x4 micro-tile
__device__ __forceinline__ void sgemm_body(const float* __restrict__ A,
                                           const float* __restrict__ W,
                                           const float* __restrict__ bias,
                                           float* __restrict__ C, int M, int N) {
    __shared__ float As[16][132];
    __shared__ float Bs[16][64];
    int tid = threadIdx.x;
    int tx = tid & 15, ty = tid >> 4;
    int m0 = blockIdx.y * 128, n0 = blockIdx.x * 64;

    float acc[8][4];
#pragma unroll
    for (int i = 0; i < 8; i++)
#pragma unroll
        for (int j = 0; j < 4; j++) acc[i][j] = 0.f;

    float bb[4] = {0.f, 0.f, 0.f, 0.f};
    if (bias) {
#pragma unroll
        for (int j = 0; j < 4; j++) bb[j] = bias[n0 + tx * 4 + j];
    }

    for (int k0 = 0; k0 < 128; k0 += 16) {
        // load A tile (transposed to As[k][m])
#pragma unroll
        for (int i = 0; i < 2; i++) {
            int slot = tid + i * 256;          // 512 float4 slots
            int row = slot >> 2, c4 = slot & 3;
            float4 v = make_float4(0.f, 0.f, 0.f, 0.f);
            if (m0 + row < M)
                v = *(const float4*)(A + (size_t)(m0 + row) * 128 + k0 + c4 * 4);
            As[c4 * 4 + 0][row] = v.x;
            As[c4 * 4 + 1][row] = v.y;
            As[c4 * 4 + 2][row] = v.z;
            As[c4 * 4 + 3][row] = v.w;
        }
        // load B tile: Bs[k][n] = W[n0+n][k0+k]
#pragma unroll
        for (int i = 0; i < 4; i++) {
            int n = (tid >> 4) + i * 16;
            int k = tid & 15;
            Bs[k][n] = W[(size_t)(n0 + n) * 128 + k0 + k];
        }
        __syncthreads();
#pragma unroll
        for (int kk = 0; kk < 16; kk++) {
            float a[8], b[4];
            *(float4*)&a[0] = *(const float4*)&As[kk][ty * 8];
            *(float4*)&a[4] = *(const float4*)&As[kk][ty * 8 + 4];
            *(float4*)&b[0] = *(const float4*)&Bs[kk][tx * 4];
#pragma unroll
            for (int i = 0; i < 8; i++)
#pragma unroll
                for (int j = 0; j < 4; j++) acc[i][j] += a[i] * b[j];
        }
        __syncthreads();
    }
#pragma unroll
    for (int i = 0; i < 8; i++) {
        int m = m0 + ty * 8 + i;
        if (m < M) {
            float4 o;
            o.x = acc[i][0] + bb[0];
            o.y = acc[i][1] + bb[1];
            o.z = acc[i][2] + bb[2];
            o.w = acc[i][3] + bb[3];
            *(float4*)(C + (size_t)m * N + n0 + tx * 4) = o;
        }
    }
}

__global__ __launch_bounds__(256) void sgemm_node(const float* __restrict__ A) {
    sgemm_body(A, g_Wstack, nullptr, g_KV, NN * 4, 512);
}
__global__ __launch_bounds__(256) void sgemm_q(const float* __restrict__ A,
                                               const float* __restrict__ W,
                                               const float* __restrict__ bias) {
    sgemm_body(A, W, bias, g_QL, EN, 128);
}

// ---------------- 5) fused edge kernel (2 edges / 256-thread block) ---------
// NOTE: edge_index is int32 on device (JAX default x64-disabled downcasts
// jnp.int64 -> int32). Reading it as int64 was the Round-1 IMA.
__global__ __launch_bounds__(256) void edge_kernel(const float* __restrict__ x,
                                                   const int* __restrict__ ei,
                                                   const float* __restrict__ bo_g,
                                                   float* __restrict__ out) {
    const float SC = 0.08838834764831845f;  // 1/sqrt(128)
    int sub = threadIdx.x >> 7;             // edge within block
    int h = threadIdx.x & 127;
    int w = (threadIdx.x >> 5) & 3;         // warp within 128-group
    int lane = threadIdx.x & 31;
    size_t e = (size_t)blockIdx.x * 2 + sub;

    int i0 = ei[e];
    int i1 = ei[EN + e];

    float q  = g_QL[e * 128 + h];
    float xe = x[e * 128 + h];

    const float* src = g_KV + (size_t)i0 * 2048;
    const float* dst = g_KV + (size_t)i1 * 2048;

    float ks[4], kd[4], vs[4], vd[4], gm[4];
#pragma unroll
    for (int s = 0; s < 4; s++) {
        ks[s] = src[s * 512 + h];
        vs[s] = src[s * 512 + 128 + h];
        kd[s] = dst[s * 512 + 256 + h];
        vd[s] = dst[s * 512 + 384 + h];
        gm[s] = g_Gmat[h * 4 + s];
    }

    float r[8];
#pragma unroll
    for (int s = 0; s < 4; s++) {
        r[s]     = q * (ks[s] + kd[s]);   // local logit partial (bk drops out of softmax)
        r[4 + s] = xe * gm[s];            // global logit partial
    }
#pragma unroll
    for (int off = 16; off > 0; off >>= 1)
#pragma unroll
        for (int j = 0; j < 8; j++) r[j] += __shfl_xor_sync(0xffffffffu, r[j], off);

    __shared__ float red[2][4][8];
    if (lane == 0) {
#pragma unroll
        for (int j = 0; j < 8; j++) red[sub][w][j] = r[j];
    }
    __syncthreads();

    float tot[8];
#pragma unroll
    for (int j = 0; j < 8; j++)
        tot[j] = red[sub][0][j] + red[sub][1][j] + red[sub][2][j] + red[sub][3][j];

    // local softmax over 4
    float sl[4], a[4];
    float m1 = -1e30f;
#pragma unroll
    for (int s = 0; s < 4; s++) { sl[s] = tot[s] * SC; m1 = fmaxf(m1, sl[s]); }
    float den = 0.f;
#pragma unroll
    for (int s = 0; s < 4; s++) { a[s] = expf(sl[s] - m1); den += a[s]; }
    float inv = 1.f / den;
#pragma unroll
    for (int s = 0; s < 4; s++) a[s] *= inv;

    // global softmax over 4
    float sg[4], ag[4];
    float m2 = -1e30f;
#pragma unroll
    for (int s = 0; s < 4; s++) { sg[s] = (tot[4 + s] + g_cg[s]) * SC; m2 = fmaxf(m2, sg[s]); }
    float den2 = 0.f;
#pragma unroll
    for (int s = 0; s < 4; s++) { ag[s] = expf(sg[s] - m2); den2 += ag[s]; }
    float inv2 = 1.f / den2;
#pragma unroll
    for (int s = 0; s < 4; s++) ag[s] *= inv2;

    float lo = g_cvec[h];
#pragma unroll
    for (int s = 0; s < 4; s++) lo += a[s] * (vs[s] + vd[s]);

    float go = bo_g[h];
#pragma unroll
    for (int s = 0; s < 4; s++) go += ag[s] * g_Mg[s * 128 + h];

    out[e * 384 + h]       = xe;
    out[e * 384 + 128 + h] = lo;
    out[e * 384 + 256 + h] = go;
    if (h < 4) out[(size_t)EN * 384 + 512 + e * 4 + h] = ag[h];
}

// ---------------- launch --------------------------------------------------
extern "C" void kernel_launch(void* const* d_in, const int* in_sizes, int n_in,
                              void* d_out, int out_size) {
    const float* edge_attr = (const float*)d_in[0];
    const float* gf        = (const float*)d_in[1];
    const int*   ei        = (const int*)d_in[2];   // int32 (JAX x64 disabled)
    const float* wq_l = (const float*)d_in[3];
    const float* wk_l = (const float*)d_in[4];
    const float* wv_l = (const float*)d_in[5];
    const float* bq_l = (const float*)d_in[6];
    // bk_l (d_in[7]) cancels in softmax; bv_l folded below
    const float* bv_l = (const float*)d_in[8];
    const float* wo_l = (const float*)d_in[9];
    const float* bo_l = (const float*)d_in[10];
    const float* wq_g = (const float*)d_in[11];
    const float* wk_g = (const float*)d_in[12];
    const float* wv_g = (const float*)d_in[13];
    const float* bq_g = (const float*)d_in[14];
    const float* bk_g = (const float*)d_in[15];
    const float* bv_g = (const float*)d_in[16];
    const float* wo_g = (const float*)d_in[17];
    const float* bo_g = (const float*)d_in[18];
    float* out = (float*)d_out;

    pool_partial<<<PBLK, 512>>>(gf);
    pre_small<<<1, 128>>>(wk_g, wv_g, wq_g, wo_g, bk_g, bv_g, bq_g, wo_l, bv_l, bo_l, out);
    build_wstack<<<512, 128>>>(wk_l, wv_l, wo_l);
    {
        dim3 grid(512 / 64, (NN * 4 + 127) / 128);
        sgemm_node<<<grid, 256>>>(gf);
    }
    {
        dim3 grid(128 / 64, (EN + 127) / 128);
        sgemm_q<<<grid, 256>>>(edge_attr, wq_l, bq_l);
    }
    edge_kernel<<<EN / 2, 256>>>(edge_attr, ei, bo_g, out);
}

// round 3
// speedup vs baseline: 1.6341x; 1.6341x over previous
#include <cuda_runtime.h>
#include <math.h>
#include <stdint.h>

#define EN   100000
#define NN   50000
#define HIDN 128
#define PBLK 256   // pooled-reduce partial blocks

// ---------------- scratch (static device arrays; no runtime alloc) ----------
__device__ float g_KV[(size_t)NN * 4 * 512];   // per (node,s): [Ks(128) VWs(128) Kd(128) VWd(128)]
__device__ float g_QL[(size_t)EN * HIDN];      // q_l per edge
__device__ float g_Wstack[512 * 128];          // stacked folded weights (N=512, K=128)
__device__ float g_pp[PBLK * 512];             // pooled partials
__device__ float g_Mg[512];                    // v_g @ wo_g^T  [s][h]
__device__ float g_Gmat[512];                  // [j][s]: wq_g^T @ k_g^T
__device__ float g_cg[4];                      // bq_g . k_g[s]
__device__ float g_cvec[128];                  // wo_l@bv_l + bo_l

__device__ __forceinline__ uint32_t f2tf32(float f) {
    uint32_t o;
    asm("cvt.rna.tf32.f32 %0, %1;" : "=r"(o) : "f"(f));
    return o;
}

// ---------------- 1) pooled mean: partial sums (deterministic 2-stage) ------
__global__ void pool_partial(const float* __restrict__ gf) {
    int b = blockIdx.x, t = threadIdx.x;          // 512 threads
    int rowsPer = (NN + PBLK - 1) / PBLK;
    int r0 = b * rowsPer;
    int r1 = min(NN, r0 + rowsPer);
    float acc = 0.f;
    for (int r = r0; r < r1; r++) acc += gf[(size_t)r * 512 + t];
    g_pp[b * 512 + t] = acc;
}

// ---------------- 2) small precompute (1 block, 512 threads) ----------------
__global__ __launch_bounds__(512) void pre_small(
        const float* __restrict__ wk_g, const float* __restrict__ wv_g,
        const float* __restrict__ wq_g, const float* __restrict__ wo_g,
        const float* __restrict__ bk_g, const float* __restrict__ bv_g,
        const float* __restrict__ bq_g,
        const float* __restrict__ wo_l, const float* __restrict__ bv_l,
        const float* __restrict__ bo_l,
        float* __restrict__ dout) {
    __shared__ float sp[512], skg[512], svg[512];
    int t = threadIdx.x;
    // reduce partials (fixed order = deterministic), write pooled output
    {
        float s = 0.f;
#pragma unroll 4
        for (int b = 0; b < PBLK; b++) s += g_pp[b * 512 + t];
        float p = s * (1.0f / NN);
        sp[t] = p;
        dout[(size_t)EN * 384 + t] = p;   // pooled_global output
    }
    __syncthreads();
    // k_g, v_g
    {
        int s = t >> 7, h = t & 127;
        float a = 0.f, bsum = 0.f;
        const float* pr = &sp[s * 128];
#pragma unroll 8
        for (int j = 0; j < 128; j++) {
            float p = pr[j];
            a    += p * wk_g[h * 128 + j];
            bsum += p * wv_g[h * 128 + j];
        }
        skg[t] = a + bk_g[h];
        svg[t] = bsum + bv_g[h];
    }
    __syncthreads();
    // M_g[s][h] = sum_j v_g[s,j] * wo_g[h,j]
    {
        int s = t >> 7, h = t & 127;
        float m = 0.f;
#pragma unroll 8
        for (int j = 0; j < 128; j++) m += svg[s * 128 + j] * wo_g[h * 128 + j];
        g_Mg[t] = m;
    }
    // Gmat[j][s] = sum_h wq_g[h,j] * k_g[s,h]
    {
        int j = t >> 2, s = t & 3;
        float g = 0.f;
#pragma unroll 8
        for (int h2 = 0; h2 < 128; h2++) g += wq_g[h2 * 128 + j] * skg[s * 128 + h2];
        g_Gmat[t] = g;
    }
    if (t < 4) {
        float c = 0.f;
        for (int h2 = 0; h2 < 128; h2++) c += bq_g[h2] * skg[t * 128 + h2];
        g_cg[t] = c;
    }
    // cvec = wo_l @ bv_l + bo_l
    if (t < 128) {
        float c = 0.f;
        for (int m = 0; m < 128; m++) c += wo_l[t * 128 + m] * bv_l[m];
        g_cvec[t] = c + bo_l[t];
    }
}

// ---------------- 3) build stacked weight matrix (512 x 128) ----------------
__global__ void build_wstack(const float* __restrict__ wk_l, const float* __restrict__ wv_l,
                             const float* __restrict__ wo_l) {
    int n = blockIdx.x, k = threadIdx.x;
    float w;
    if (n < 128) {
        w = wk_l[n * 256 + k];
    } else if (n < 256) {
        int h = n - 128; float s = 0.f;
        for (int m = 0; m < 128; m++) s += wo_l[h * 128 + m] * wv_l[m * 256 + k];
        w = s;
    } else if (n < 384) {
        w = wk_l[(n - 256) * 256 + 128 + k];
    } else {
        int h = n - 384; float s = 0.f;
        for (int m = 0; m < 128; m++) s += wo_l[h * 128 + m] * wv_l[m * 256 + 128 + k];
        w = s;
    }
    g_Wstack[n * 128 + k] = w;
}

// ---------------- 4) tf32 tensor-core GEMM ----------------------------------
// C[M,N] = A[M,128] @ W[N,128]^T (+bias).  BM=128 BN=128 BK=32, 256 threads.
// mma.sync.m16n8k8.tf32, fp32 accumulate; inputs rounded to tf32 at SMEM fill.
#define AS_STRIDE 36

__device__ __forceinline__ void mma_tf32(float c[4], const uint32_t a[4], const uint32_t b[2]) {
    asm volatile(
        "mma.sync.aligned.m16n8k8.row.col.f32.tf32.tf32.f32 "
        "{%0,%1,%2,%3}, {%4,%5,%6,%7}, {%8,%9}, {%0,%1,%2,%3};\n"
        : "+f"(c[0]), "+f"(c[1]), "+f"(c[2]), "+f"(c[3])
        : "r"(a[0]), "r"(a[1]), "r"(a[2]), "r"(a[3]), "r"(b[0]), "r"(b[1]));
}

__device__ __forceinline__ void gemm_tc_body(const float* __restrict__ A,
                                             const float* __restrict__ W,
                                             const float* __restrict__ bias,
                                             float* __restrict__ C, int M, int N) {
    __shared__ uint32_t As[128 * AS_STRIDE];
    __shared__ uint32_t Bs[128 * AS_STRIDE];

    int tid  = threadIdx.x;
    int lane = tid & 31, wid = tid >> 5;
    int wm = wid & 3, wn = wid >> 2;          // warps 4 (M) x 2 (N)
    int mw = wm * 32, nw = wn * 64;
    int m0 = blockIdx.y * 128, n0 = blockIdx.x * 128;
    int g  = lane >> 2, tg = lane & 3;        // groupID, threadID-in-group

    float acc[2][8][4];
#pragma unroll
    for (int mi = 0; mi < 2; mi++)
#pragma unroll
        for (int ni = 0; ni < 8; ni++)
#pragma unroll
            for (int j = 0; j < 4; j++) acc[mi][ni][j] = 0.f;

    for (int k0 = 0; k0 < 128; k0 += 32) {
        // ---- load A tile [128 rows][32 cols] as tf32 ----
#pragma unroll
        for (int i = 0; i < 4; i++) {
            int slot = tid + i * 256;          // 1024 float4 slots
            int row = slot >> 3, c4 = slot & 7;
            float4 v = make_float4(0.f, 0.f, 0.f, 0.f);
            if (m0 + row < M)
                v = *(const float4*)(A + (size_t)(m0 + row) * 128 + k0 + c4 * 4);
            uint32_t* d = &As[row * AS_STRIDE + c4 * 4];
            d[0] = f2tf32(v.x); d[1] = f2tf32(v.y);
            d[2] = f2tf32(v.z); d[3] = f2tf32(v.w);
        }
        // ---- load B tile: Bs[n][k] = W[n0+n][k0+k] as tf32 ----
#pragma unroll
        for (int i = 0; i < 4; i++) {
            int slot = tid + i * 256;
            int row = slot >> 3, c4 = slot & 7;
            float4 v = *(const float4*)(W + (size_t)(n0 + row) * 128 + k0 + c4 * 4);
            uint32_t* d = &Bs[row * AS_STRIDE + c4 * 4];
            d[0] = f2tf32(v.x); d[1] = f2tf32(v.y);
            d[2] = f2tf32(v.z); d[3] = f2tf32(v.w);
        }
        __syncthreads();

#pragma unroll
        for (int kk = 0; kk < 32; kk += 8) {
            uint32_t a[2][4], b[8][2];
#pragma unroll
            for (int mi = 0; mi < 2; mi++) {
                const uint32_t* base = &As[(mw + mi * 16 + g) * AS_STRIDE + kk + tg];
                a[mi][0] = base[0];
                a[mi][1] = base[8 * AS_STRIDE];
                a[mi][2] = base[4];
                a[mi][3] = base[8 * AS_STRIDE + 4];
            }
#pragma unroll
            for (int ni = 0; ni < 8; ni++) {
                const uint32_t* base = &Bs[(nw + ni * 8 + g) * AS_STRIDE + kk + tg];
                b[ni][0] = base[0];
                b[ni][1] = base[4];
            }
#pragma unroll
            for (int mi = 0; mi < 2; mi++)
#pragma unroll
                for (int ni = 0; ni < 8; ni++)
                    mma_tf32(acc[mi][ni], a[mi], b[ni]);
        }
        __syncthreads();
    }

    // ---- epilogue ----
#pragma unroll
    for (int ni = 0; ni < 8; ni++) {
        int n = n0 + nw + ni * 8 + 2 * tg;
        float b0 = 0.f, b1 = 0.f;
        if (bias) { b0 = bias[n]; b1 = bias[n + 1]; }
#pragma unroll
        for (int mi = 0; mi < 2; mi++) {
            int m = m0 + mw + mi * 16 + g;
            if (m < M) {
                float2 o0 = make_float2(acc[mi][ni][0] + b0, acc[mi][ni][1] + b1);
                *(float2*)(C + (size_t)m * N + n) = o0;
            }
            if (m + 8 < M) {
                float2 o1 = make_float2(acc[mi][ni][2] + b0, acc[mi][ni][3] + b1);
                *(float2*)(C + (size_t)(m + 8) * N + n) = o1;
            }
        }
    }
}

__global__ __launch_bounds__(256) void gemm_node(const float* __restrict__ A) {
    gemm_tc_body(A, g_Wstack, nullptr, g_KV, NN * 4, 512);
}
__global__ __launch_bounds__(256) void gemm_q(const float* __restrict__ A,
                                              const float* __restrict__ W,
                                              const float* __restrict__ bias) {
    gemm_tc_body(A, W, bias, g_QL, EN, 128);
}

// ---------------- 5) fused edge kernel (2 edges / 256-thread block) ---------
__global__ __launch_bounds__(256) void edge_kernel(const float* __restrict__ x,
                                                   const int* __restrict__ ei,
                                                   const float* __restrict__ bo_g,
                                                   float* __restrict__ out) {
    const float SC = 0.08838834764831845f;  // 1/sqrt(128)
    int sub = threadIdx.x >> 7;             // edge within block
    int h = threadIdx.x & 127;
    int w = (threadIdx.x >> 5) & 3;         // warp within 128-group
    int lane = threadIdx.x & 31;
    size_t e = (size_t)blockIdx.x * 2 + sub;

    int i0 = ei[e];
    int i1 = ei[EN + e];

    float q  = g_QL[e * 128 + h];
    float xe = x[e * 128 + h];

    const float* src = g_KV + (size_t)i0 * 2048;
    const float* dst = g_KV + (size_t)i1 * 2048;

    float ks[4], kd[4], vs[4], vd[4], gm[4];
#pragma unroll
    for (int s = 0; s < 4; s++) {
        ks[s] = src[s * 512 + h];
        vs[s] = src[s * 512 + 128 + h];
        kd[s] = dst[s * 512 + 256 + h];
        vd[s] = dst[s * 512 + 384 + h];
        gm[s] = g_Gmat[h * 4 + s];
    }

    float r[8];
#pragma unroll
    for (int s = 0; s < 4; s++) {
        r[s]     = q * (ks[s] + kd[s]);   // local logit partial (bk drops out of softmax)
        r[4 + s] = xe * gm[s];            // global logit partial
    }
#pragma unroll
    for (int off = 16; off > 0; off >>= 1)
#pragma unroll
        for (int j = 0; j < 8; j++) r[j] += __shfl_xor_sync(0xffffffffu, r[j], off);

    __shared__ float red[2][4][8];
    if (lane == 0) {
#pragma unroll
        for (int j = 0; j < 8; j++) red[sub][w][j] = r[j];
    }
    __syncthreads();

    float tot[8];
#pragma unroll
    for (int j = 0; j < 8; j++)
        tot[j] = red[sub][0][j] + red[sub][1][j] + red[sub][2][j] + red[sub][3][j];

    // local softmax over 4
    float sl[4], a[4];
    float m1 = -1e30f;
#pragma unroll
    for (int s = 0; s < 4; s++) { sl[s] = tot[s] * SC; m1 = fmaxf(m1, sl[s]); }
    float den = 0.f;
#pragma unroll
    for (int s = 0; s < 4; s++) { a[s] = expf(sl[s] - m1); den += a[s]; }
    float inv = 1.f / den;
#pragma unroll
    for (int s = 0; s < 4; s++) a[s] *= inv;

    // global softmax over 4
    float sg[4], ag[4];
    float m2 = -1e30f;
#pragma unroll
    for (int s = 0; s < 4; s++) { sg[s] = (tot[4 + s] + g_cg[s]) * SC; m2 = fmaxf(m2, sg[s]); }
    float den2 = 0.f;
#pragma unroll
    for (int s = 0; s < 4; s++) { ag[s] = expf(sg[s] - m2); den2 += ag[s]; }
    float inv2 = 1.f / den2;
#pragma unroll
    for (int s = 0; s < 4; s++) ag[s] *= inv2;

    float lo = g_cvec[h];
#pragma unroll
    for (int s = 0; s < 4; s++) lo += a[s] * (vs[s] + vd[s]);

    float go = bo_g[h];
#pragma unroll
    for (int s = 0; s < 4; s++) go += ag[s] * g_Mg[s * 128 + h];

    out[e * 384 + h]       = xe;
    out[e * 384 + 128 + h] = lo;
    out[e * 384 + 256 + h] = go;
    if (h < 4) out[(size_t)EN * 384 + 512 + e * 4 + h] = ag[h];
}

// ---------------- launch --------------------------------------------------
extern "C" void kernel_launch(void* const* d_in, const int* in_sizes, int n_in,
                              void* d_out, int out_size) {
    const float* edge_attr = (const float*)d_in[0];
    const float* gf        = (const float*)d_in[1];
    const int*   ei        = (const int*)d_in[2];   // int32 (JAX x64 disabled)
    const float* wq_l = (const float*)d_in[3];
    const float* wk_l = (const float*)d_in[4];
    const float* wv_l = (const float*)d_in[5];
    const float* bq_l = (const float*)d_in[6];
    // bk_l (d_in[7]) cancels in softmax; bv_l folded below
    const float* bv_l = (const float*)d_in[8];
    const float* wo_l = (const float*)d_in[9];
    const float* bo_l = (const float*)d_in[10];
    const float* wq_g = (const float*)d_in[11];
    const float* wk_g = (const float*)d_in[12];
    const float* wv_g = (const float*)d_in[13];
    const float* bq_g = (const float*)d_in[14];
    const float* bk_g = (const float*)d_in[15];
    const float* bv_g = (const float*)d_in[16];
    const float* wo_g = (const float*)d_in[17];
    const float* bo_g = (const float*)d_in[18];
    float* out = (float*)d_out;

    pool_partial<<<PBLK, 512>>>(gf);
    pre_small<<<1, 512>>>(wk_g, wv_g, wq_g, wo_g, bk_g, bv_g, bq_g, wo_l, bv_l, bo_l, out);
    build_wstack<<<512, 128>>>(wk_l, wv_l, wo_l);
    {
        dim3 grid(512 / 128, (NN * 4 + 127) / 128);   // (4, 1563)
        gemm_node<<<grid, 256>>>(gf);
    }
    {
        dim3 grid(128 / 128, (EN + 127) / 128);       // (1, 782)
        gemm_q<<<grid, 256>>>(edge_attr, wq_l, bq_l);
    }
    edge_kernel<<<EN / 2, 256>>>(edge_attr, ei, bo_g, out);
}